// round 14
// baseline (speedup 1.0000x reference)
#include <cuda_runtime.h>
#include <cstdint>

#define BB   16
#define CC   256
#define HH   64
#define WW   192
#define DD   25
#define HWs  (HH*WW)
#define CHW  (512*HH*WW)
#define X2OFF ((size_t)CC*HWs)

// smem staging geometry (floats)
#define S1    196                 // x1 row stride (conflict-free frag LDS)
#define S2    228                 // x2 row stride (24-col zero front pad + 192 data)
#define X1F   (16*S1)
#define BUFF  (16*S1 + 16*S2)     // 6784 floats
#define NBUF  4
#define SMEM_BYTES (NBUF*BUFF*4)  // 108544
#define SLABW 196                 // slab stride; data cols 4..195 (16B aligned), pads at 3,196
#define NCH   8                   // chunks per CTA (half the channels)

// partial horizontal 3-sums, one per channel-half
__device__ float g_hs0[(size_t)BB*DD*HH*WW];
__device__ float g_hs1[(size_t)BB*DD*HH*WW];

__device__ __forceinline__ uint32_t smem_u32(const void* p) {
    uint32_t a;
    asm("{ .reg .u64 t; cvta.to.shared.u64 t, %1; cvt.u32.u64 %0, t; }" : "=r"(a) : "l"(p));
    return a;
}
__device__ __forceinline__ void cp_async16(uint32_t dst, const void* src) {
    asm volatile("cp.async.cg.shared.global [%0], [%1], 16;\n" :: "r"(dst), "l"(src));
}
// split f0,f1 into packed bf16x2 hi and lo (lo16 of reg = f0, hi16 = f1)
__device__ __forceinline__ void split2(float f0, float f1, uint32_t& hi, uint32_t& lo) {
    asm("cvt.rn.bf16x2.f32 %0, %1, %2;" : "=r"(hi) : "f"(f1), "f"(f0));
    float l0 = f0 - __uint_as_float(hi << 16);
    float l1 = f1 - __uint_as_float(hi & 0xffff0000u);
    asm("cvt.rn.bf16x2.f32 %0, %1, %2;" : "=r"(lo) : "f"(l1), "f"(l0));
}
__device__ __forceinline__ void mma_bf16(float* d, const uint32_t* a, const uint32_t* b) {
    asm volatile("mma.sync.aligned.m16n8k16.row.col.f32.bf16.bf16.f32 "
        "{%0,%1,%2,%3}, {%4,%5,%6,%7}, {%8,%9}, {%0,%1,%2,%3};"
        : "+f"(d[0]), "+f"(d[1]), "+f"(d[2]), "+f"(d[3])
        : "r"(a[0]), "r"(a[1]), "r"(a[2]), "r"(a[3]), "r"(b[0]), "r"(b[1]));
}

// CTA per (h, b, channel-half z): D_z[w][n] = sum_{c in half z} x1[c][w]*x2pad[c][n].
__global__ void __launch_bounds__(384, 2) corr_mma(const float* __restrict__ in) {
    extern __shared__ float sm[];

    const int t   = threadIdx.x;
    const int m   = t >> 5;
    const int lid = t & 31;
    const int g   = lid >> 2;
    const int tg  = lid & 3;
    const int h   = blockIdx.x, b = blockIdx.y, z = blockIdx.z;

    const float* x1 = in + (size_t)b * CHW + (size_t)h * WW + (size_t)(z * NCH * 16) * HWs;
    const float* x2 = x1 + X2OFF;

    // zero the 24-col front pads of all buffers once
    for (int i = t; i < NBUF * 16 * 24; i += 384) {
        int bu  = i / (16 * 24);
        int rem = i - bu * 16 * 24;
        int row = rem / 24, col = rem - row * 24;
        sm[bu * BUFF + X1F + row * S2 + col] = 0.f;
    }

    // staging map: 2 float4 rows of x1 + 2 of x2 per thread per chunk
    const int r0 = t / 48,          c40 = t - r0 * 48;
    const int r1 = (t + 384) / 48,  c41 = (t + 384) - r1 * 48;
    const size_t so0 = (size_t)r0 * HWs + c40 * 4;
    const size_t so1 = (size_t)r1 * HWs + c41 * 4;
    const uint32_t smbase = smem_u32(sm);
    const uint32_t d0 = smbase + (r0 * S1 + c40 * 4) * 4;
    const uint32_t d1 = smbase + (r1 * S1 + c41 * 4) * 4;
    const uint32_t d2 = smbase + (X1F + r0 * S2 + 24 + c40 * 4) * 4;
    const uint32_t d3 = smbase + (X1F + r1 * S2 + 24 + c41 * 4) * 4;

#define ISSUE(buf, ch) do {                                                    \
    const size_t _co = (size_t)(ch) * 16 * HWs;                                \
    const uint32_t _bo = (buf) * (BUFF * 4);                                   \
    cp_async16(d0 + _bo, x1 + _co + so0);                                      \
    cp_async16(d1 + _bo, x1 + _co + so1);                                      \
    cp_async16(d2 + _bo, x2 + _co + so0);                                      \
    cp_async16(d3 + _bo, x2 + _co + so1);                                      \
    asm volatile("cp.async.commit_group;\n");                                  \
} while (0)

    float acc[5][4];
    #pragma unroll
    for (int tt = 0; tt < 5; tt++)
        #pragma unroll
        for (int q = 0; q < 4; q++) acc[tt][q] = 0.f;

    const int wA = 16 * m + g;
    const int k0 = 2 * tg;

    ISSUE(0, 0);
    ISSUE(1, 1);
    ISSUE(2, 2);

    int buf = 0;
    #pragma unroll 1
    for (int ch = 0; ch < NCH; ch++) {
        if (ch < NCH - 2)      asm volatile("cp.async.wait_group 2;\n");
        else if (ch < NCH - 1) asm volatile("cp.async.wait_group 1;\n");
        else                   asm volatile("cp.async.wait_group 0;\n");
        __syncthreads();
        if (ch + 3 < NCH) {
            int nb = buf + 3; if (nb >= NBUF) nb -= NBUF;
            ISSUE(nb, ch + 3);
        }

        const int X1B = buf * BUFF;
        const int X2B = buf * BUFF + X1F;

        uint32_t Ah[4], Al[4];
        split2(sm[X1B + k0 * S1 + wA],           sm[X1B + (k0 + 1) * S1 + wA],     Ah[0], Al[0]);
        split2(sm[X1B + k0 * S1 + wA + 8],       sm[X1B + (k0 + 1) * S1 + wA + 8], Ah[1], Al[1]);
        split2(sm[X1B + (k0 + 8) * S1 + wA],     sm[X1B + (k0 + 9) * S1 + wA],     Ah[2], Al[2]);
        split2(sm[X1B + (k0 + 8) * S1 + wA + 8], sm[X1B + (k0 + 9) * S1 + wA + 8], Ah[3], Al[3]);

        #pragma unroll
        for (int tt = 0; tt < 5; tt++) {
            const int nB = 16 * m + 8 * tt + g;   // padded x2 col
            uint32_t Bh[2], Bl[2];
            split2(sm[X2B + k0 * S2 + nB],       sm[X2B + (k0 + 1) * S2 + nB], Bh[0], Bl[0]);
            split2(sm[X2B + (k0 + 8) * S2 + nB], sm[X2B + (k0 + 9) * S2 + nB], Bh[1], Bl[1]);
            mma_bf16(acc[tt], Ah, Bh);
            mma_bf16(acc[tt], Al, Bh);
            mma_bf16(acc[tt], Ah, Bl);
        }
        if (++buf >= NBUF) buf = 0;
    }
#undef ISSUE

    // epilogue: scatter to slab (conflict-free), fuse horizontal 3-sum into coalesced store.
    // Slab sits in buffer 0/1 region; last chunk (ch=7) used buffer 3 — disjoint.
    float* slab = sm;
    if (t < 2 * DD) {
        int d = t >> 1;
        slab[d * SLABW + ((t & 1) ? 196 : 3)] = 0.f;   // col196 aliases row d+1 cols<3 (unused)
    }
    #pragma unroll
    for (int tt = 0; tt < 5; tt++) {
        int n0 = 8 * (2 * m + tt) + 2 * tg;
        #pragma unroll
        for (int q = 0; q < 4; q++) {
            int w = wA + ((q >= 2) ? 8 : 0);
            int n = n0 + (q & 1);
            int d = w + 24 - n;
            if (d >= 0 && d < DD)
                slab[d * SLABW + 4 + w] = acc[tt][q];
        }
    }
    __syncthreads();
    {
        float* dstbuf = z ? g_hs1 : g_hs0;
        const size_t pb = ((size_t)b * DD * HH + h) * WW;
        #pragma unroll 1
        for (int idx = t; idx < DD * 48; idx += 384) {
            int d  = idx / 48;
            int c4 = idx - d * 48;
            const float* p = &slab[d * SLABW + 4 + c4 * 4];
            float4 v = *(const float4*)p;
            float lft = p[-1], rgt = p[4];
            float4 hs;
            hs.x = lft + v.x + v.y;
            hs.y = v.x + v.y + v.z;
            hs.z = v.y + v.z + v.w;
            hs.w = v.z + v.w + rgt;
            *(float4*)(dstbuf + pb + (size_t)d * HWs + c4 * 4) = hs;
        }
    }
}

// ---------------- box: vertical 3-sum of (g_hs0 + g_hs1), 2 h-rows per thread ----------------
#define TPB2 256

__device__ __forceinline__ float4 add4(float4 a, float4 b) {
    return make_float4(a.x + b.x, a.y + b.y, a.z + b.z, a.w + b.w);
}

__global__ __launch_bounds__(TPB2)
void box_kernel(float* __restrict__ out) {
    const int plane = blockIdx.y;                         // b*25 + d
    const int idx = blockIdx.x * TPB2 + threadIdx.x;      // 0..1535
    const int hp  = idx / 48;                             // h-pair 0..31
    const int w0  = (idx - hp * 48) * 4;
    const int h0  = hp * 2;

    const size_t off = (size_t)plane * HWs + w0;
    const float* p0 = g_hs0 + off;
    const float* p1 = g_hs1 + off;

    float4 vm = make_float4(0.f, 0.f, 0.f, 0.f);
    if (h0 > 0)
        vm = add4(__ldg((const float4*)(p0 + (h0 - 1) * WW)), __ldg((const float4*)(p1 + (h0 - 1) * WW)));
    float4 v0 = add4(__ldg((const float4*)(p0 + h0 * WW)),       __ldg((const float4*)(p1 + h0 * WW)));
    float4 v1 = add4(__ldg((const float4*)(p0 + (h0 + 1) * WW)), __ldg((const float4*)(p1 + (h0 + 1) * WW)));
    float4 vp = make_float4(0.f, 0.f, 0.f, 0.f);
    if (h0 + 2 < HH)
        vp = add4(__ldg((const float4*)(p0 + (h0 + 2) * WW)), __ldg((const float4*)(p1 + (h0 + 2) * WW)));

    float* op = out + off;
    *(float4*)(op + h0 * WW)       = add4(add4(vm, v0), v1);
    *(float4*)(op + (h0 + 1) * WW) = add4(add4(v0, v1), vp);
}

extern "C" void kernel_launch(void* const* d_in, const int* in_sizes, int n_in,
                              void* d_out, int out_size) {
    const float* in = (const float*)d_in[0];
    float* out = (float*)d_out;

    cudaFuncSetAttribute(corr_mma, cudaFuncAttributeMaxDynamicSharedMemorySize, SMEM_BYTES);
    dim3 g1(HH, BB, 2);                 // 2048 CTAs
    corr_mma<<<g1, 384, SMEM_BYTES>>>(in);

    dim3 g2(6, BB * DD);                // 2400 blocks: 1536 threads/plane
    box_kernel<<<g2, TPB2>>>(out);
}

// round 15
// speedup vs baseline: 1.0231x; 1.0231x over previous
#include <cuda_runtime.h>
#include <cstdint>

#define BB   16
#define CC   256
#define HH   64
#define WW   192
#define DD   25
#define HWs  (HH*WW)
#define CHW  (512*HH*WW)
#define X2OFF ((size_t)CC*HWs)

// smem staging geometry (floats)
#define S1    196                 // x1 row stride (conflict-free frag LDS)
#define S2    228                 // x2 row stride (24-col zero front pad + 192 data)
#define X1F   (16*S1)
#define BUFF  (16*S1 + 16*S2)     // 6784 floats
#define NBUF  4
#define SMEM_BYTES (NBUF*BUFF*4)  // 108544
#define SLABW 196                 // slab stride; data cols 4..195 (16B aligned), pads at 3,196

// g_hs[b][d][h][w] = horizontal 3-sum of corr
__device__ float g_hs[(size_t)BB*DD*HH*WW];

__device__ __forceinline__ uint32_t smem_u32(const void* p) {
    uint32_t a;
    asm("{ .reg .u64 t; cvta.to.shared.u64 t, %1; cvt.u32.u64 %0, t; }" : "=r"(a) : "l"(p));
    return a;
}
__device__ __forceinline__ void cp_async16(uint32_t dst, const void* src) {
    asm volatile("cp.async.cg.shared.global [%0], [%1], 16;\n" :: "r"(dst), "l"(src));
}
// split f0,f1 into packed bf16x2 hi and lo (lo16 of reg = f0, hi16 = f1)
__device__ __forceinline__ void split2(float f0, float f1, uint32_t& hi, uint32_t& lo) {
    asm("cvt.rn.bf16x2.f32 %0, %1, %2;" : "=r"(hi) : "f"(f1), "f"(f0));
    float l0 = f0 - __uint_as_float(hi << 16);
    float l1 = f1 - __uint_as_float(hi & 0xffff0000u);
    asm("cvt.rn.bf16x2.f32 %0, %1, %2;" : "=r"(lo) : "f"(l1), "f"(l0));
}
__device__ __forceinline__ void mma_bf16(float* d, const uint32_t* a, const uint32_t* b) {
    asm volatile("mma.sync.aligned.m16n8k16.row.col.f32.bf16.bf16.f32 "
        "{%0,%1,%2,%3}, {%4,%5,%6,%7}, {%8,%9}, {%0,%1,%2,%3};"
        : "+f"(d[0]), "+f"(d[1]), "+f"(d[2]), "+f"(d[3])
        : "r"(a[0]), "r"(a[1]), "r"(a[2]), "r"(a[3]), "r"(b[0]), "r"(b[1]));
}

// D[w][n] = sum_c x1[c][w] * x2pad[c][n], n = w + 24 - d.  CTA per (b,h), warp m: w-tile [16m,16m+16).
__global__ void __launch_bounds__(384, 2) corr_mma(const float* __restrict__ in) {
    extern __shared__ float sm[];

    const int t   = threadIdx.x;
    const int m   = t >> 5;
    const int lid = t & 31;
    const int g   = lid >> 2;
    const int tg  = lid & 3;
    const int h   = blockIdx.x, b = blockIdx.y;

    const float* x1 = in + (size_t)b * CHW + (size_t)h * WW;
    const float* x2 = x1 + X2OFF;

    // zero the 24-col front pads of all buffers once
    for (int i = t; i < NBUF * 16 * 24; i += 384) {
        int bu  = i / (16 * 24);
        int rem = i - bu * 16 * 24;
        int row = rem / 24, col = rem - row * 24;
        sm[bu * BUFF + X1F + row * S2 + col] = 0.f;
    }

    // staging map: 2 float4 rows of x1 + 2 of x2 per thread per chunk
    const int r0 = t / 48,          c40 = t - r0 * 48;
    const int r1 = (t + 384) / 48,  c41 = (t + 384) - r1 * 48;
    const size_t so0 = (size_t)r0 * HWs + c40 * 4;
    const size_t so1 = (size_t)r1 * HWs + c41 * 4;
    const uint32_t smbase = smem_u32(sm);
    const uint32_t d0 = smbase + (r0 * S1 + c40 * 4) * 4;
    const uint32_t d1 = smbase + (r1 * S1 + c41 * 4) * 4;
    const uint32_t d2 = smbase + (X1F + r0 * S2 + 24 + c40 * 4) * 4;
    const uint32_t d3 = smbase + (X1F + r1 * S2 + 24 + c41 * 4) * 4;

#define ISSUE(buf, ch) do {                                                    \
    const size_t _co = (size_t)(ch) * 16 * HWs;                                \
    const uint32_t _bo = (buf) * (BUFF * 4);                                   \
    cp_async16(d0 + _bo, x1 + _co + so0);                                      \
    cp_async16(d1 + _bo, x1 + _co + so1);                                      \
    cp_async16(d2 + _bo, x2 + _co + so0);                                      \
    cp_async16(d3 + _bo, x2 + _co + so1);                                      \
    asm volatile("cp.async.commit_group;\n");                                  \
} while (0)

    float acc[5][4];
    #pragma unroll
    for (int tt = 0; tt < 5; tt++)
        #pragma unroll
        for (int q = 0; q < 4; q++) acc[tt][q] = 0.f;

    const int wA = 16 * m + g;
    const int k0 = 2 * tg;

    ISSUE(0, 0);
    ISSUE(1, 1);
    ISSUE(2, 2);

    int buf = 0;
    #pragma unroll 1
    for (int ch = 0; ch < 16; ch++) {
        if (ch < 14)      asm volatile("cp.async.wait_group 2;\n");
        else if (ch < 15) asm volatile("cp.async.wait_group 1;\n");
        else              asm volatile("cp.async.wait_group 0;\n");
        __syncthreads();
        if (ch + 3 < 16) {
            int nb = buf + 3; if (nb >= NBUF) nb -= NBUF;
            ISSUE(nb, ch + 3);
        }

        const int X1B = buf * BUFF;
        const int X2B = buf * BUFF + X1F;

        uint32_t Ah[4], Al[4];
        split2(sm[X1B + k0 * S1 + wA],           sm[X1B + (k0 + 1) * S1 + wA],     Ah[0], Al[0]);
        split2(sm[X1B + k0 * S1 + wA + 8],       sm[X1B + (k0 + 1) * S1 + wA + 8], Ah[1], Al[1]);
        split2(sm[X1B + (k0 + 8) * S1 + wA],     sm[X1B + (k0 + 9) * S1 + wA],     Ah[2], Al[2]);
        split2(sm[X1B + (k0 + 8) * S1 + wA + 8], sm[X1B + (k0 + 9) * S1 + wA + 8], Ah[3], Al[3]);

        #pragma unroll
        for (int tt = 0; tt < 5; tt++) {
            const int nB = 16 * m + 8 * tt + g;   // padded x2 col
            uint32_t Bh[2], Bl[2];
            split2(sm[X2B + k0 * S2 + nB],       sm[X2B + (k0 + 1) * S2 + nB], Bh[0], Bl[0]);
            split2(sm[X2B + (k0 + 8) * S2 + nB], sm[X2B + (k0 + 9) * S2 + nB], Bh[1], Bl[1]);
            mma_bf16(acc[tt], Ah, Bh);
            mma_bf16(acc[tt], Al, Bh);
            mma_bf16(acc[tt], Ah, Bl);
        }
        if (++buf >= NBUF) buf = 0;
    }
#undef ISSUE

    // epilogue: scatter accs into slab (conflict-free banks), zero pads at cols 3/196,
    // horizontal 3-sum fused into the coalesced store.
    float* slab = sm;
    if (t < 2 * DD) {
        int d = t >> 1;
        slab[d * SLABW + ((t & 1) ? 196 : 3)] = 0.f;   // col196 aliases row d+1 cols<3 (unused)
    }
    #pragma unroll
    for (int tt = 0; tt < 5; tt++) {
        int n0 = 8 * (2 * m + tt) + 2 * tg;
        #pragma unroll
        for (int q = 0; q < 4; q++) {
            int w = wA + ((q >= 2) ? 8 : 0);
            int n = n0 + (q & 1);
            int d = w + 24 - n;
            if (d >= 0 && d < DD)
                slab[d * SLABW + 4 + w] = acc[tt][q];
        }
    }
    __syncthreads();
    {
        const size_t pb = ((size_t)b * DD * HH + h) * WW;   // (b, d=0, h, 0)
        #pragma unroll 1
        for (int idx = t; idx < DD * 48; idx += 384) {
            int d  = idx / 48;
            int c4 = idx - d * 48;
            const float* p = &slab[d * SLABW + 4 + c4 * 4];  // 16B aligned
            float4 v = *(const float4*)p;
            float lft = p[-1], rgt = p[4];
            float4 hs;
            hs.x = lft + v.x + v.y;
            hs.y = v.x + v.y + v.z;
            hs.z = v.y + v.z + v.w;
            hs.w = v.z + v.w + rgt;
            *(float4*)(g_hs + pb + (size_t)d * HWs + c4 * 4) = hs;
        }
    }
}

// ---------------- box: vertical 3-sum over g_hs, 4 h-rows per thread ----------------
#define TPB2 256

__device__ __forceinline__ float4 add4(float4 a, float4 b) {
    return make_float4(a.x + b.x, a.y + b.y, a.z + b.z, a.w + b.w);
}

__global__ __launch_bounds__(TPB2)
void box_kernel(float* __restrict__ out) {
    const int plane = blockIdx.y;                         // b*25 + d
    const int idx = blockIdx.x * TPB2 + threadIdx.x;      // 0..767
    const int hq  = idx / 48;                             // h-quad 0..15
    const int w0  = (idx - hq * 48) * 4;
    const int h0  = hq * 4;

    const float* p = g_hs + (size_t)plane * HWs + w0;

    float4 vm = make_float4(0.f, 0.f, 0.f, 0.f);
    if (h0 > 0) vm = __ldg((const float4*)(p + (h0 - 1) * WW));
    float4 v0 = __ldg((const float4*)(p + (h0 + 0) * WW));
    float4 v1 = __ldg((const float4*)(p + (h0 + 1) * WW));
    float4 v2 = __ldg((const float4*)(p + (h0 + 2) * WW));
    float4 v3 = __ldg((const float4*)(p + (h0 + 3) * WW));
    float4 vp = make_float4(0.f, 0.f, 0.f, 0.f);
    if (h0 + 4 < HH) vp = __ldg((const float4*)(p + (h0 + 4) * WW));

    float* op = out + (size_t)plane * HWs + w0;
    *(float4*)(op + (h0 + 0) * WW) = add4(add4(vm, v0), v1);
    *(float4*)(op + (h0 + 1) * WW) = add4(add4(v0, v1), v2);
    *(float4*)(op + (h0 + 2) * WW) = add4(add4(v1, v2), v3);
    *(float4*)(op + (h0 + 3) * WW) = add4(add4(v2, v3), vp);
}

extern "C" void kernel_launch(void* const* d_in, const int* in_sizes, int n_in,
                              void* d_out, int out_size) {
    const float* in = (const float*)d_in[0];
    float* out = (float*)d_out;

    cudaFuncSetAttribute(corr_mma, cudaFuncAttributeMaxDynamicSharedMemorySize, SMEM_BYTES);
    dim3 g1(HH, BB);                    // 1024 CTAs
    corr_mma<<<g1, 384, SMEM_BYTES>>>(in);

    dim3 g2(3, BB * DD);                // 1200 blocks: 768 threads/plane, 4 rows/thread
    box_kernel<<<g2, TPB2>>>(out);
}

// round 17
// speedup vs baseline: 1.0382x; 1.0147x over previous
#include <cuda_runtime.h>
#include <cstdint>

#define BB   16
#define CC   256
#define HH   64
#define WW   192
#define DD   25
#define HWs  (HH*WW)
#define CHW  (512*HH*WW)
#define X2OFF ((size_t)CC*HWs)

// smem staging geometry (floats)
#define S1    196                 // x1 row stride (conflict-free frag LDS)
#define S2    228                 // x2 row stride (24-col zero front pad + 192 data)
#define X1F   (16*S1)
#define BUFF  (16*S1 + 16*S2)     // 6784 floats
#define NBUF  4
#define SMEM_BYTES (NBUF*BUFF*4)  // 108544
#define SLABW 196                 // slab stride; data cols 4..195 (16B aligned), pads at 3,196

// g_hs[b][d][h][w] = horizontal 3-sum of corr
__device__ float g_hs[(size_t)BB*DD*HH*WW];

__device__ __forceinline__ uint32_t smem_u32(const void* p) {
    uint32_t a;
    asm("{ .reg .u64 t; cvta.to.shared.u64 t, %1; cvt.u32.u64 %0, t; }" : "=r"(a) : "l"(p));
    return a;
}
__device__ __forceinline__ void cp_async16(uint32_t dst, const void* src) {
    asm volatile("cp.async.cg.shared.global [%0], [%1], 16;\n" :: "r"(dst), "l"(src));
}
// split f0,f1 into packed bf16x2 hi and lo (lo16 of reg = f0, hi16 = f1)
__device__ __forceinline__ void split2(float f0, float f1, uint32_t& hi, uint32_t& lo) {
    asm("cvt.rn.bf16x2.f32 %0, %1, %2;" : "=r"(hi) : "f"(f1), "f"(f0));
    float l0 = f0 - __uint_as_float(hi << 16);
    float l1 = f1 - __uint_as_float(hi & 0xffff0000u);
    asm("cvt.rn.bf16x2.f32 %0, %1, %2;" : "=r"(lo) : "f"(l1), "f"(l0));
}
__device__ __forceinline__ void mma_bf16(float* d, const uint32_t* a, const uint32_t* b) {
    asm volatile("mma.sync.aligned.m16n8k16.row.col.f32.bf16.bf16.f32 "
        "{%0,%1,%2,%3}, {%4,%5,%6,%7}, {%8,%9}, {%0,%1,%2,%3};"
        : "+f"(d[0]), "+f"(d[1]), "+f"(d[2]), "+f"(d[3])
        : "r"(a[0]), "r"(a[1]), "r"(a[2]), "r"(a[3]), "r"(b[0]), "r"(b[1]));
}

// D[w][n] = sum_c x1[c][w] * x2pad[c][n], n = w + 24 - d.  CTA per (b,h), warp m: w-tile [16m,16m+16).
__global__ void __launch_bounds__(384, 2) corr_mma(const float* __restrict__ in) {
    extern __shared__ float sm[];

    const int t   = threadIdx.x;
    const int m   = t >> 5;
    const int lid = t & 31;
    const int g   = lid >> 2;
    const int tg  = lid & 3;
    const int h   = blockIdx.x, b = blockIdx.y;

    const float* x1 = in + (size_t)b * CHW + (size_t)h * WW;
    const float* x2 = x1 + X2OFF;

    // zero the 24-col front pads of all buffers once
    for (int i = t; i < NBUF * 16 * 24; i += 384) {
        int bu  = i / (16 * 24);
        int rem = i - bu * 16 * 24;
        int row = rem / 24, col = rem - row * 24;
        sm[bu * BUFF + X1F + row * S2 + col] = 0.f;
    }

    // staging map: 2 float4 rows of x1 + 2 of x2 per thread per chunk
    const int r0 = t / 48,          c40 = t - r0 * 48;
    const int r1 = (t + 384) / 48,  c41 = (t + 384) - r1 * 48;
    const size_t so0 = (size_t)r0 * HWs + c40 * 4;
    const size_t so1 = (size_t)r1 * HWs + c41 * 4;
    const uint32_t smbase = smem_u32(sm);
    const uint32_t d0 = smbase + (r0 * S1 + c40 * 4) * 4;
    const uint32_t d1 = smbase + (r1 * S1 + c41 * 4) * 4;
    const uint32_t d2 = smbase + (X1F + r0 * S2 + 24 + c40 * 4) * 4;
    const uint32_t d3 = smbase + (X1F + r1 * S2 + 24 + c41 * 4) * 4;

#define ISSUE(buf, ch) do {                                                    \
    const size_t _co = (size_t)(ch) * 16 * HWs;                                \
    const uint32_t _bo = (buf) * (BUFF * 4);                                   \
    cp_async16(d0 + _bo, x1 + _co + so0);                                      \
    cp_async16(d1 + _bo, x1 + _co + so1);                                      \
    cp_async16(d2 + _bo, x2 + _co + so0);                                      \
    cp_async16(d3 + _bo, x2 + _co + so1);                                      \
    asm volatile("cp.async.commit_group;\n");                                  \
} while (0)

    float acc[5][4];
    #pragma unroll
    for (int tt = 0; tt < 5; tt++)
        #pragma unroll
        for (int q = 0; q < 4; q++) acc[tt][q] = 0.f;

    const int wA = 16 * m + g;
    const int k0 = 2 * tg;

    ISSUE(0, 0);
    ISSUE(1, 1);
    ISSUE(2, 2);

    int buf = 0;
    #pragma unroll 1
    for (int ch = 0; ch < 16; ch++) {
        if (ch < 14)      asm volatile("cp.async.wait_group 2;\n");
        else if (ch < 15) asm volatile("cp.async.wait_group 1;\n");
        else              asm volatile("cp.async.wait_group 0;\n");
        __syncthreads();
        if (ch + 3 < 16) {
            int nb = buf + 3; if (nb >= NBUF) nb -= NBUF;
            ISSUE(nb, ch + 3);
        }

        const int X1B = buf * BUFF;
        const int X2B = buf * BUFF + X1F;

        uint32_t Ah[4], Al[4];
        split2(sm[X1B + k0 * S1 + wA],           sm[X1B + (k0 + 1) * S1 + wA],     Ah[0], Al[0]);
        split2(sm[X1B + k0 * S1 + wA + 8],       sm[X1B + (k0 + 1) * S1 + wA + 8], Ah[1], Al[1]);
        split2(sm[X1B + (k0 + 8) * S1 + wA],     sm[X1B + (k0 + 9) * S1 + wA],     Ah[2], Al[2]);
        split2(sm[X1B + (k0 + 8) * S1 + wA + 8], sm[X1B + (k0 + 9) * S1 + wA + 8], Ah[3], Al[3]);

        #pragma unroll
        for (int tt = 0; tt < 5; tt++) {
            const int nB = 16 * m + 8 * tt + g;   // padded x2 col
            uint32_t Bh[2], Bl[2];
            split2(sm[X2B + k0 * S2 + nB],       sm[X2B + (k0 + 1) * S2 + nB], Bh[0], Bl[0]);
            split2(sm[X2B + (k0 + 8) * S2 + nB], sm[X2B + (k0 + 9) * S2 + nB], Bh[1], Bl[1]);
            mma_bf16(acc[tt], Ah, Bh);
            mma_bf16(acc[tt], Al, Bh);
            mma_bf16(acc[tt], Ah, Bl);
        }
        if (++buf >= NBUF) buf = 0;
    }
#undef ISSUE

    // epilogue: scatter accs into slab (conflict-free banks), zero pads at cols 3/196,
    // horizontal 3-sum fused into the coalesced store.
    float* slab = sm;
    if (t < 2 * DD) {
        int d = t >> 1;
        slab[d * SLABW + ((t & 1) ? 196 : 3)] = 0.f;   // col196 aliases row d+1 cols<3 (unused)
    }
    #pragma unroll
    for (int tt = 0; tt < 5; tt++) {
        int n0 = 8 * (2 * m + tt) + 2 * tg;
        #pragma unroll
        for (int q = 0; q < 4; q++) {
            int w = wA + ((q >= 2) ? 8 : 0);
            int n = n0 + (q & 1);
            int d = w + 24 - n;
            if (d >= 0 && d < DD)
                slab[d * SLABW + 4 + w] = acc[tt][q];
        }
    }
    __syncthreads();
    {
        const size_t pb = ((size_t)b * DD * HH + h) * WW;   // (b, d=0, h, 0)
        #pragma unroll 1
        for (int idx = t; idx < DD * 48; idx += 384) {
            int d  = idx / 48;
            int c4 = idx - d * 48;
            const float* p = &slab[d * SLABW + 4 + c4 * 4];  // 16B aligned
            float4 v = *(const float4*)p;
            float lft = p[-1], rgt = p[4];
            float4 hs;
            hs.x = lft + v.x + v.y;
            hs.y = v.x + v.y + v.z;
            hs.z = v.y + v.z + v.w;
            hs.w = v.z + v.w + rgt;
            *(float4*)(g_hs + pb + (size_t)d * HWs + c4 * 4) = hs;
        }
    }
}

// ---------------- box: vertical 3-sum over g_hs, 8 h-rows per thread ----------------
#define TPB2 256
#define PLANE_ITEMS 384            // 8 h-octets * 48 w-quads

__device__ __forceinline__ float4 add4(float4 a, float4 b) {
    return make_float4(a.x + b.x, a.y + b.y, a.z + b.z, a.w + b.w);
}
// streaming store (evict-first): out is never re-read
__device__ __forceinline__ void stg_cs(float* p, float4 v) {
    asm volatile("st.global.cs.v4.f32 [%0], {%1,%2,%3,%4};"
                 :: "l"(p), "f"(v.x), "f"(v.y), "f"(v.z), "f"(v.w) : "memory");
}

__global__ __launch_bounds__(TPB2)
void box_kernel(float* __restrict__ out) {
    const int plane = blockIdx.y;                         // b*25 + d
    const int idx = blockIdx.x * TPB2 + threadIdx.x;
    if (idx >= PLANE_ITEMS) return;                       // guard: grid covers 512 slots
    const int ho  = idx / 48;                             // h-octet 0..7
    const int w0  = (idx - ho * 48) * 4;
    const int h0  = ho * 8;

    const float* p = g_hs + (size_t)plane * HWs + w0;

    float4 v[10];
    v[0] = make_float4(0.f, 0.f, 0.f, 0.f);
    if (h0 > 0) v[0] = __ldg((const float4*)(p + (h0 - 1) * WW));
    #pragma unroll
    for (int r = 0; r < 8; r++)
        v[r + 1] = __ldg((const float4*)(p + (h0 + r) * WW));
    v[9] = make_float4(0.f, 0.f, 0.f, 0.f);
    if (h0 + 8 < HH) v[9] = __ldg((const float4*)(p + (h0 + 8) * WW));

    float* op = out + (size_t)plane * HWs + w0;
    #pragma unroll
    for (int r = 0; r < 8; r++)
        stg_cs(op + (h0 + r) * WW, add4(add4(v[r], v[r + 1]), v[r + 2]));
}

extern "C" void kernel_launch(void* const* d_in, const int* in_sizes, int n_in,
                              void* d_out, int out_size) {
    const float* in = (const float*)d_in[0];
    float* out = (float*)d_out;

    cudaFuncSetAttribute(corr_mma, cudaFuncAttributeMaxDynamicSharedMemorySize, SMEM_BYTES);
    dim3 g1(HH, BB);                    // 1024 CTAs
    corr_mma<<<g1, 384, SMEM_BYTES>>>(in);

    dim3 g2((PLANE_ITEMS + TPB2 - 1) / TPB2, BB * DD);   // (2, 400), tail-guarded
    box_kernel<<<g2, TPB2>>>(out);
}